// round 3
// baseline (speedup 1.0000x reference)
#include <cuda_runtime.h>

// Causal prefill attention: q,k,v [B,H,L,D] fp32 -> out [B,H,L,D] fp32
// B=2 H=16 L=2048 D=128, scale = 1/sqrt(D).
// Flash-attention-2 style: one CTA per (head, 64-row query tile), online softmax,
// K/V tiles streamed through shared memory, register-blocked fp32 GEMMs.

namespace {
constexpr int kB = 2, kH = 16, kL = 2048, kD = 128;
constexpr int BR = 64;          // query tile rows
constexpr int BC = 64;          // key tile cols
constexpr int QSTR = 132;       // padded row stride (floats) for Q/K/V tiles
constexpr int PSTR = 68;        // padded row stride (floats) for P tile
constexpr int NTHR = 256;       // 16 x 16 thread grid
constexpr float kScale = 0.08838834764831845f;  // 1/sqrt(128)
}

__global__ __launch_bounds__(NTHR, 1)
void fa_causal_fp32_kernel(const float* __restrict__ gq,
                           const float* __restrict__ gk,
                           const float* __restrict__ gv,
                           float* __restrict__ gout) {
    extern __shared__ float sm[];
    float* Qs = sm;                      // [BR][QSTR]
    float* Ks = Qs + BR * QSTR;          // [BC][QSTR]
    float* Vs = Ks + BC * QSTR;          // [BC][QSTR]
    float* Pp = Vs + BC * QSTR;          // [BR][PSTR]

    const int tid = threadIdx.x;
    const int tx  = tid & 15;            // 0..15  -> S cols {tx, tx+16, tx+32, tx+48}
    const int ty  = tid >> 4;            // 0..15  -> S rows {4ty .. 4ty+3}
    const int it  = blockIdx.x;          // query tile index
    const int bh  = blockIdx.y;          // fused (b,h)
    const size_t base = (size_t)bh * kL * kD;
    const int q0 = it * BR;

    // ---- load Q tile (coalesced float4, conflict-free smem writes) ----
    #pragma unroll
    for (int i = 0; i < (BR * kD / 4) / NTHR; ++i) {
        int lin = tid + i * NTHR;        // 0..2047
        int r   = lin >> 5;              // row 0..63
        int d4  = (lin & 31) << 2;       // 0,4,..,124
        *reinterpret_cast<float4*>(&Qs[r * QSTR + d4]) =
            *reinterpret_cast<const float4*>(&gq[base + (size_t)(q0 + r) * kD + d4]);
    }

    // ---- accumulators ----
    float o[4][8];                       // O micro-tile: rows 4ty+r, cols {4tx+c, 64+4tx+c}
    float mrow[4], lrow[4];
    #pragma unroll
    for (int r = 0; r < 4; ++r) {
        mrow[r] = -1e30f;
        lrow[r] = 0.0f;
        #pragma unroll
        for (int c = 0; c < 8; ++c) o[r][c] = 0.0f;
    }

    for (int jt = 0; jt <= it; ++jt) {
        const int k0 = jt * BC;

        __syncthreads();  // previous iteration done reading Ks/Vs/Pp
        #pragma unroll
        for (int i = 0; i < (BC * kD / 4) / NTHR; ++i) {
            int lin = tid + i * NTHR;
            int r   = lin >> 5;
            int d4  = (lin & 31) << 2;
            *reinterpret_cast<float4*>(&Ks[r * QSTR + d4]) =
                *reinterpret_cast<const float4*>(&gk[base + (size_t)(k0 + r) * kD + d4]);
            *reinterpret_cast<float4*>(&Vs[r * QSTR + d4]) =
                *reinterpret_cast<const float4*>(&gv[base + (size_t)(k0 + r) * kD + d4]);
        }
        __syncthreads();

        // ---- GEMM1: S = Q K^T  (rows 4ty+r, cols tx+16c) ----
        float s[4][4];
        #pragma unroll
        for (int r = 0; r < 4; ++r)
            #pragma unroll
            for (int c = 0; c < 4; ++c) s[r][c] = 0.0f;

        #pragma unroll 8
        for (int kk = 0; kk < kD; kk += 4) {
            float4 qv[4], kv[4];
            #pragma unroll
            for (int r = 0; r < 4; ++r)
                qv[r] = *reinterpret_cast<const float4*>(&Qs[(4 * ty + r) * QSTR + kk]);
            #pragma unroll
            for (int c = 0; c < 4; ++c)
                kv[c] = *reinterpret_cast<const float4*>(&Ks[(tx + 16 * c) * QSTR + kk]);
            #pragma unroll
            for (int r = 0; r < 4; ++r)
                #pragma unroll
                for (int c = 0; c < 4; ++c) {
                    s[r][c] += qv[r].x * kv[c].x;
                    s[r][c] += qv[r].y * kv[c].y;
                    s[r][c] += qv[r].z * kv[c].z;
                    s[r][c] += qv[r].w * kv[c].w;
                }
        }

        // ---- scale + causal mask (only the diagonal tile is partial) ----
        const bool diag = (jt == it);
        float mloc[4];
        #pragma unroll
        for (int r = 0; r < 4; ++r) {
            mloc[r] = -1e30f;
            const int rowl = 4 * ty + r;
            #pragma unroll
            for (int c = 0; c < 4; ++c) {
                float val = s[r][c] * kScale;
                if (diag && (tx + 16 * c) > rowl) val = -1e30f;
                s[r][c] = val;
                mloc[r] = fmaxf(mloc[r], val);
            }
        }
        // reduce max across the 16-lane tx group
        #pragma unroll
        for (int off = 8; off > 0; off >>= 1) {
            #pragma unroll
            for (int r = 0; r < 4; ++r)
                mloc[r] = fmaxf(mloc[r], __shfl_xor_sync(0xffffffffu, mloc[r], off));
        }

        float alpha[4], rs[4];
        #pragma unroll
        for (int r = 0; r < 4; ++r) {
            float mnew = fmaxf(mrow[r], mloc[r]);
            alpha[r] = __expf(mrow[r] - mnew);
            mrow[r] = mnew;
            rs[r] = 0.0f;
            #pragma unroll
            for (int c = 0; c < 4; ++c) {
                float p = __expf(s[r][c] - mnew);
                Pp[(4 * ty + r) * PSTR + tx + 16 * c] = p;
                rs[r] += p;
            }
        }
        #pragma unroll
        for (int off = 8; off > 0; off >>= 1) {
            #pragma unroll
            for (int r = 0; r < 4; ++r)
                rs[r] += __shfl_xor_sync(0xffffffffu, rs[r], off);
        }
        #pragma unroll
        for (int r = 0; r < 4; ++r) {
            lrow[r] = lrow[r] * alpha[r] + rs[r];
            #pragma unroll
            for (int c = 0; c < 8; ++c) o[r][c] *= alpha[r];
        }
        __syncthreads();  // Pp visible to all

        // ---- GEMM2: O += P V  (rows 4ty+r, cols {4tx..4tx+3, 64+4tx..64+4tx+3}) ----
        #pragma unroll 4
        for (int k4 = 0; k4 < BC; k4 += 4) {
            float4 pv[4];
            #pragma unroll
            for (int r = 0; r < 4; ++r)
                pv[r] = *reinterpret_cast<const float4*>(&Pp[(4 * ty + r) * PSTR + k4]);
            float pa[4][4];
            #pragma unroll
            for (int r = 0; r < 4; ++r) {
                pa[r][0] = pv[r].x; pa[r][1] = pv[r].y;
                pa[r][2] = pv[r].z; pa[r][3] = pv[r].w;
            }
            #pragma unroll
            for (int kk = 0; kk < 4; ++kk) {
                float4 va = *reinterpret_cast<const float4*>(&Vs[(k4 + kk) * QSTR + 4 * tx]);
                float4 vb = *reinterpret_cast<const float4*>(&Vs[(k4 + kk) * QSTR + 64 + 4 * tx]);
                #pragma unroll
                for (int r = 0; r < 4; ++r) {
                    float p = pa[r][kk];
                    o[r][0] += p * va.x; o[r][1] += p * va.y;
                    o[r][2] += p * va.z; o[r][3] += p * va.w;
                    o[r][4] += p * vb.x; o[r][5] += p * vb.y;
                    o[r][6] += p * vb.z; o[r][7] += p * vb.w;
                }
            }
        }
    }

    // ---- finalize: O /= l, write out ----
    #pragma unroll
    for (int r = 0; r < 4; ++r) {
        const float inv = 1.0f / lrow[r];
        const size_t row_off = base + (size_t)(q0 + 4 * ty + r) * kD;
        float4 a, b;
        a.x = o[r][0] * inv; a.y = o[r][1] * inv; a.z = o[r][2] * inv; a.w = o[r][3] * inv;
        b.x = o[r][4] * inv; b.y = o[r][5] * inv; b.z = o[r][6] * inv; b.w = o[r][7] * inv;
        *reinterpret_cast<float4*>(&gout[row_off + 4 * tx])      = a;
        *reinterpret_cast<float4*>(&gout[row_off + 64 + 4 * tx]) = b;
    }
}

extern "C" void kernel_launch(void* const* d_in, const int* in_sizes, int n_in,
                              void* d_out, int out_size) {
    (void)in_sizes; (void)n_in; (void)out_size;
    const float* q = (const float*)d_in[0];
    const float* k = (const float*)d_in[1];
    const float* v = (const float*)d_in[2];
    float* out = (float*)d_out;

    const size_t smem = (size_t)(3 * BR * QSTR + BR * PSTR) * sizeof(float);  // 118784 B
    cudaFuncSetAttribute(fa_causal_fp32_kernel,
                         cudaFuncAttributeMaxDynamicSharedMemorySize, (int)smem);

    dim3 grid(kL / BR, kB * kH);  // (32 query tiles, 32 heads)
    fa_causal_fp32_kernel<<<grid, NTHR, smem>>>(q, k, v, out);
}

// round 4
// speedup vs baseline: 2.6749x; 2.6749x over previous
#include <cuda_runtime.h>

// Causal prefill attention, q,k,v,out: [B,H,L,D] fp32. B=2 H=16 L=2048 D=128.
// Flash-attention-2 with tf32 tensor-core MMA (mma.sync.m16n8k8).
// CTA = 256 threads (8 warps), BR=128 query rows, BC=64 keys per iteration.
// Each warp owns 16 full query rows -> softmax is warp-local.
// Inputs rounded to tf32 (cvt.rna) once when staged to smem; fp32 accumulation.

namespace {
constexpr int kL = 2048, kD = 128;
constexpr int BR = 128, BC = 64, NTHR = 256;
constexpr int QSTR = 132;   // Q/K smem row stride (floats): stride%32==4 -> conflict-free frags
constexpr int KSTR = 132;
constexpr int VSTR = 136;   // V stride%32==8 -> conflict-free for V B-fragment pattern
constexpr int PSTR = 68;    // P stride%32==4
// (1/sqrt(128)) * log2(e): softmax done in base-2 so exp is a single MUFU EX2
constexpr float kScaleLog2 = 0.12751745210670913f;
}

__device__ __forceinline__ float to_tf32(float x) {
    unsigned u;
    asm("cvt.rna.tf32.f32 %0, %1;" : "=r"(u) : "f"(x));
    return __uint_as_float(u);
}

__device__ __forceinline__ void mma_tf32(float c[4], const float a[4], float b0f, float b1f) {
    unsigned A0 = __float_as_uint(a[0]), A1 = __float_as_uint(a[1]);
    unsigned A2 = __float_as_uint(a[2]), A3 = __float_as_uint(a[3]);
    unsigned B0 = __float_as_uint(b0f), B1 = __float_as_uint(b1f);
    asm volatile(
        "mma.sync.aligned.m16n8k8.row.col.f32.tf32.tf32.f32 "
        "{%0,%1,%2,%3}, {%4,%5,%6,%7}, {%8,%9}, {%0,%1,%2,%3};\n"
        : "+f"(c[0]), "+f"(c[1]), "+f"(c[2]), "+f"(c[3])
        : "r"(A0), "r"(A1), "r"(A2), "r"(A3), "r"(B0), "r"(B1));
}

__global__ __launch_bounds__(NTHR, 1)
void fa_tf32_kernel(const float* __restrict__ gq,
                    const float* __restrict__ gk,
                    const float* __restrict__ gv,
                    float* __restrict__ gout) {
    extern __shared__ float sm[];
    float* Qs = sm;                      // [BR][QSTR]
    float* Ks = Qs + BR * QSTR;          // [BC][KSTR]
    float* Vs = Ks + BC * KSTR;          // [BC][VSTR]
    float* Ps = Vs + BC * VSTR;          // 8 x [16][PSTR] (per-warp)

    const int tid  = threadIdx.x;
    const int lane = tid & 31;
    const int wid  = tid >> 5;
    const int g    = lane >> 2;          // group id (0..7)
    const int lq   = lane & 3;           // lane-in-group (0..3)
    // heavy tiles first: reverse the q-tile index to shrink the causal tail
    const int it = (int)gridDim.x - 1 - (int)blockIdx.x;
    const int bh = blockIdx.y;
    const size_t base = (size_t)bh * kL * kD;
    const int q0 = it * BR;

    // ---- stage Q (tf32-rounded), coalesced 512B per warp-instruction ----
    #pragma unroll
    for (int i = 0; i < (BR * kD / 4) / NTHR; ++i) {   // 16
        int lin = tid + i * NTHR;
        int r = lin >> 5, d4 = (lin & 31) << 2;
        float4 t = *reinterpret_cast<const float4*>(&gq[base + (size_t)(q0 + r) * kD + d4]);
        t.x = to_tf32(t.x); t.y = to_tf32(t.y); t.z = to_tf32(t.z); t.w = to_tf32(t.w);
        *reinterpret_cast<float4*>(&Qs[r * QSTR + d4]) = t;
    }

    float o[16][4];
    #pragma unroll
    for (int j = 0; j < 16; ++j) { o[j][0] = o[j][1] = o[j][2] = o[j][3] = 0.f; }
    float m0 = -1e30f, m1 = -1e30f;      // running max (log2 domain)
    float l0 = 0.f, l1 = 0.f;            // running denom

    float* Pw = Ps + wid * 16 * PSTR;
    const int Rg = wid * 16 + g;         // this thread's first row within CTA tile
    const int row0 = q0 + Rg, row1 = row0 + 8;

    const int njt = 2 * it + 2;
    for (int jt = 0; jt < njt; ++jt) {
        const int k0 = jt * BC;

        __syncthreads();   // prior iteration done with Ks/Vs
        #pragma unroll
        for (int i = 0; i < (BC * kD / 4) / NTHR; ++i) {   // 8
            int lin = tid + i * NTHR;
            int r = lin >> 5, d4 = (lin & 31) << 2;
            float4 tk = *reinterpret_cast<const float4*>(&gk[base + (size_t)(k0 + r) * kD + d4]);
            float4 tv = *reinterpret_cast<const float4*>(&gv[base + (size_t)(k0 + r) * kD + d4]);
            tk.x = to_tf32(tk.x); tk.y = to_tf32(tk.y); tk.z = to_tf32(tk.z); tk.w = to_tf32(tk.w);
            tv.x = to_tf32(tv.x); tv.y = to_tf32(tv.y); tv.z = to_tf32(tv.z); tv.w = to_tf32(tv.w);
            *reinterpret_cast<float4*>(&Ks[r * KSTR + d4]) = tk;
            *reinterpret_cast<float4*>(&Vs[r * VSTR + d4]) = tv;
        }
        __syncthreads();

        // ---- GEMM1: S[16x64] = Q Kt (warp-local rows), 8 n-tiles, 16 k-steps ----
        float s[8][4];
        #pragma unroll
        for (int j = 0; j < 8; ++j) { s[j][0] = s[j][1] = s[j][2] = s[j][3] = 0.f; }

        #pragma unroll 4
        for (int kk = 0; kk < 16; ++kk) {
            float a[4];
            const float* qa = &Qs[Rg * QSTR + 8 * kk + lq];
            a[0] = qa[0];
            a[1] = qa[8 * QSTR];
            a[2] = qa[4];
            a[3] = qa[8 * QSTR + 4];
            #pragma unroll
            for (int j = 0; j < 8; ++j) {
                const float* kb = &Ks[(8 * j + g) * KSTR + 8 * kk + lq];
                mma_tf32(s[j], a, kb[0], kb[4]);
            }
        }

        // ---- scale into log2 domain + causal mask (last two iters only) ----
        const bool diag = (jt >= 2 * it);
        float t0 = -1e30f, t1 = -1e30f;
        #pragma unroll
        for (int j = 0; j < 8; ++j) {
            #pragma unroll
            for (int c = 0; c < 4; ++c) s[j][c] *= kScaleLog2;
            if (diag) {
                int col = k0 + 8 * j + 2 * lq;
                if (col     > row0) s[j][0] = -1e30f;
                if (col + 1 > row0) s[j][1] = -1e30f;
                if (col     > row1) s[j][2] = -1e30f;
                if (col + 1 > row1) s[j][3] = -1e30f;
            }
            t0 = fmaxf(t0, fmaxf(s[j][0], s[j][1]));
            t1 = fmaxf(t1, fmaxf(s[j][2], s[j][3]));
        }
        t0 = fmaxf(t0, __shfl_xor_sync(0xffffffffu, t0, 1));
        t0 = fmaxf(t0, __shfl_xor_sync(0xffffffffu, t0, 2));
        t1 = fmaxf(t1, __shfl_xor_sync(0xffffffffu, t1, 1));
        t1 = fmaxf(t1, __shfl_xor_sync(0xffffffffu, t1, 2));

        const float mn0 = fmaxf(m0, t0), mn1 = fmaxf(m1, t1);
        const float al0 = exp2f(m0 - mn0), al1 = exp2f(m1 - mn1);
        m0 = mn0; m1 = mn1;

        float rs0 = 0.f, rs1 = 0.f;
        #pragma unroll
        for (int j = 0; j < 8; ++j) {
            float p0 = exp2f(s[j][0] - mn0);
            float p1 = exp2f(s[j][1] - mn0);
            float p2 = exp2f(s[j][2] - mn1);
            float p3 = exp2f(s[j][3] - mn1);
            rs0 += p0 + p1;
            rs1 += p2 + p3;
            float2 w0; w0.x = to_tf32(p0); w0.y = to_tf32(p1);
            float2 w1; w1.x = to_tf32(p2); w1.y = to_tf32(p3);
            *reinterpret_cast<float2*>(&Pw[g * PSTR + 8 * j + 2 * lq]) = w0;
            *reinterpret_cast<float2*>(&Pw[(g + 8) * PSTR + 8 * j + 2 * lq]) = w1;
        }
        rs0 += __shfl_xor_sync(0xffffffffu, rs0, 1);
        rs0 += __shfl_xor_sync(0xffffffffu, rs0, 2);
        rs1 += __shfl_xor_sync(0xffffffffu, rs1, 1);
        rs1 += __shfl_xor_sync(0xffffffffu, rs1, 2);
        l0 = l0 * al0 + rs0;
        l1 = l1 * al1 + rs1;
        #pragma unroll
        for (int j = 0; j < 16; ++j) {
            o[j][0] *= al0; o[j][1] *= al0;
            o[j][2] *= al1; o[j][3] *= al1;
        }
        __syncwarp();   // P visible to all lanes of this warp

        // ---- GEMM2: O[16x128] += P V, 16 n-tiles, 8 k-steps ----
        #pragma unroll 2
        for (int kk = 0; kk < 8; ++kk) {
            float a[4];
            const float* pa = &Pw[g * PSTR + 8 * kk + lq];
            a[0] = pa[0];
            a[1] = pa[8 * PSTR];
            a[2] = pa[4];
            a[3] = pa[8 * PSTR + 4];
            #pragma unroll
            for (int j = 0; j < 16; ++j) {
                const float* vb = &Vs[(8 * kk + lq) * VSTR + 8 * j + g];
                mma_tf32(o[j], a, vb[0], vb[4 * VSTR]);
            }
        }
    }

    // ---- finalize: divide by l, write out (float2 per row-half) ----
    const float inv0 = 1.0f / l0;
    const float inv1 = 1.0f / l1;
    const size_t r0off = base + (size_t)row0 * kD;
    const size_t r1off = base + (size_t)row1 * kD;
    #pragma unroll
    for (int j = 0; j < 16; ++j) {
        float2 w0; w0.x = o[j][0] * inv0; w0.y = o[j][1] * inv0;
        float2 w1; w1.x = o[j][2] * inv1; w1.y = o[j][3] * inv1;
        *reinterpret_cast<float2*>(&gout[r0off + 8 * j + 2 * lq]) = w0;
        *reinterpret_cast<float2*>(&gout[r1off + 8 * j + 2 * lq]) = w1;
    }
}

extern "C" void kernel_launch(void* const* d_in, const int* in_sizes, int n_in,
                              void* d_out, int out_size) {
    (void)in_sizes; (void)n_in; (void)out_size;
    const float* q = (const float*)d_in[0];
    const float* k = (const float*)d_in[1];
    const float* v = (const float*)d_in[2];
    float* out = (float*)d_out;

    const size_t smem =
        (size_t)(BR * QSTR + BC * KSTR + BC * VSTR + 8 * 16 * PSTR) * sizeof(float); // 171008 B
    cudaFuncSetAttribute(fa_tf32_kernel,
                         cudaFuncAttributeMaxDynamicSharedMemorySize, (int)smem);

    dim3 grid(kL / BR, 32);   // 16 q-tiles x (B*H=32)
    fa_tf32_kernel<<<grid, NTHR, smem>>>(q, k, v, out);
}